// round 15
// baseline (speedup 1.0000x reference)
#include <cuda_runtime.h>
#include <cuda_bf16.h>
#include <math.h>
#include <stdint.h>

#define NE 16
#define DIM 512
#define HID 1024
#define MAXT 8192
#define MAXSLOTS (MAXT * 2)

// ---------------- scratch (device globals; no allocation allowed) ----------
__device__ int   g_cnt[NE];
__device__ int   g_tidx[MAXSLOTS];
__device__ int   g_rank[MAXSLOTS];
__device__ float g_tw[MAXSLOTS];
__device__ int   g_slot_token[MAXSLOTS];
__device__ float g_tws[MAXSLOTS];                        // weight per slot
__device__ __nv_bfloat16 g_xb[(size_t)MAXT * DIM];       // x bf16 (same layout)
__device__ __nv_bfloat16 g_hb[(size_t)MAXSLOTS * HID];   // gelu(h) bf16
// weights, k-pair packed: word(kp,n) = {lo=W[2kp][n], hi=W[2kp+1][n]} bf16x2
__device__ __nv_bfloat16 g_w1p[(size_t)NE * DIM * HID];  // [E][DIM/2][HID] words
__device__ __nv_bfloat16 g_w2p[(size_t)NE * HID * DIM];  // [E][HID/2][DIM] words

// ---------------- PTX helpers ------------------------------------------------
__device__ __forceinline__ uint32_t smem_u32(const void* p) {
    uint32_t a;
    asm("{ .reg .u64 t; cvta.to.shared.u64 t, %1; cvt.u32.u64 %0, t; }"
        : "=r"(a) : "l"(p));
    return a;
}

#define CP_ASYNC16(dst, src) \
    asm volatile("cp.async.cg.shared.global [%0], [%1], 16;" \
                 :: "r"(dst), "l"(src) : "memory")
#define CP_COMMIT() asm volatile("cp.async.commit_group;" ::: "memory")
#define CP_WAIT2()  asm volatile("cp.async.wait_group 2;"  ::: "memory")

#define MMA_BF16(c, a0, a1, a2, a3, b0, b1) \
    asm volatile("mma.sync.aligned.m16n8k16.row.col.f32.bf16.bf16.f32 " \
                 "{%0,%1,%2,%3}, {%4,%5,%6,%7}, {%8,%9}, {%0,%1,%2,%3};" \
                 : "+f"((c)[0]), "+f"((c)[1]), "+f"((c)[2]), "+f"((c)[3]) \
                 : "r"(a0), "r"(a1), "r"(a2), "r"(a3), "r"(b0), "r"(b1))

// pack {lo, hi} fp32 -> bf16x2 (src0 = hi, src1 = lo; verified rounds 7-14)
__device__ __forceinline__ uint32_t packlohi(float lo, float hi) {
    uint32_t d;
    asm("cvt.rn.bf16x2.f32 %0, %1, %2;" : "=r"(d) : "f"(hi), "f"(lo));
    return d;
}

// ---------------- router (verified r13/14) -----------------------------------
__global__ void __launch_bounds__(256)
k_router(const float* __restrict__ x, const float* __restrict__ Wr,
         const float* __restrict__ br, int T) {
    __shared__ float wrs[DIM * 17];
    for (int i = threadIdx.x; i < DIM * NE; i += 256) {
        int d = i >> 4, e = i & 15;
        wrs[d * 17 + e] = Wr[i];
    }
    __syncthreads();

    const int lane = threadIdx.x & 31;
    const int w    = threadIdx.x >> 5;
    const int q    = lane & 7;
    const int tok  = blockIdx.x * 32 + w * 4 + (lane >> 3);
    const int tokc = min(tok, T - 1);

    float acc[NE];
#pragma unroll
    for (int e = 0; e < NE; e++) acc[e] = 0.f;

    const float* xr = x + (size_t)tokc * DIM;
#pragma unroll 4
    for (int i = 0; i < DIM / 8; i++) {
        const int d = i * 8 + q;
        const float xs = xr[d];
        const float* wrow = wrs + d * 17;
#pragma unroll
        for (int e = 0; e < NE; e++) acc[e] = fmaf(xs, wrow[e], acc[e]);
    }
#pragma unroll
    for (int off = 1; off <= 4; off <<= 1)
#pragma unroll
        for (int e = 0; e < NE; e++)
            acc[e] += __shfl_xor_sync(0xffffffffu, acc[e], off);

    if (q == 0 && tok < T) {
        float l[NE];
#pragma unroll
        for (int e = 0; e < NE; e++) l[e] = acc[e] + br[e];
        int b0 = 0; float l0 = l[0];
#pragma unroll
        for (int e = 1; e < NE; e++) if (l[e] > l0) { l0 = l[e]; b0 = e; }
        int b1 = -1; float l1 = -3.0e38f;
#pragma unroll
        for (int e = 0; e < NE; e++)
            if (e != b0 && l[e] > l1) { l1 = l[e]; b1 = e; }
        float w0 = 1.f / (1.f + expf(l1 - l0));
        g_tidx[2 * tok] = b0; g_tidx[2 * tok + 1] = b1;
        g_tw[2 * tok] = w0;   g_tw[2 * tok + 1] = 1.f - w0;
        g_rank[2 * tok]     = atomicAdd(&g_cnt[b0], 1);
        g_rank[2 * tok + 1] = atomicAdd(&g_cnt[b1], 1);
    }
}

// scatter v4: inline prefix over 16 counters (replaces k_scan), no atomics
__global__ void k_scatter(int T) {
    int i = blockIdx.x * blockDim.x + threadIdx.x;
    if (i >= 2 * T) return;
    int e = g_tidx[i];
    int off = 0;
#pragma unroll
    for (int j = 0; j < NE; j++) off += (j < e) ? g_cnt[j] : 0;
    int pos = off + g_rank[i];
    g_slot_token[pos] = i >> 1;
    g_tws[pos]        = g_tw[i];
}

// merged prep: W1 pair-pack | W2 pair-pack | x -> (xb bf16, y = x) + cnt zero
__device__ __forceinline__ void pairpack(const float* __restrict__ W,
                                         __nv_bfloat16* __restrict__ Wp,
                                         int KK, int NN, int i) {
    int nq4 = NN / 4;
    int nq = i % nq4;
    int rest = i / nq4;
    int kp = rest % (KK / 2);
    int e  = rest / (KK / 2);
    const float* base = W + ((size_t)e * KK + 2 * kp) * NN + nq * 4;
    float4 r0 = *(const float4*)base;
    float4 r1 = *(const float4*)(base + NN);
    uint4 o;
    o.x = packlohi(r0.x, r1.x);
    o.y = packlohi(r0.y, r1.y);
    o.z = packlohi(r0.z, r1.z);
    o.w = packlohi(r0.w, r1.w);
    *(uint4*)(Wp + (((size_t)e * (KK / 2) + kp) * NN + nq * 4) * 2) = o;
}

#define WSEG 4096   // blocks per weight segment: NE*(K/2)*(N/4)/256 = 4096

__global__ void __launch_bounds__(256)
k_prep(const float* __restrict__ W1, const float* __restrict__ W2,
       const float* __restrict__ x,
       __nv_bfloat16* __restrict__ w1p, __nv_bfloat16* __restrict__ w2p,
       __nv_bfloat16* __restrict__ xb, float* __restrict__ y, int T) {
    int b = blockIdx.x;
    if (b < WSEG) {
        pairpack(W1, w1p, DIM, HID, b * 256 + threadIdx.x);
    } else if (b < 2 * WSEG) {
        pairpack(W2, w2p, HID, DIM, (b - WSEG) * 256 + threadIdx.x);
    } else {
        if (b == 2 * WSEG && threadIdx.x < NE) g_cnt[threadIdx.x] = 0;
        int i = (b - 2 * WSEG) * 256 + threadIdx.x;
        if (i < T * (DIM / 4)) {
            float4 v = *(const float4*)(x + (size_t)i * 4);
            uint2 o;
            o.x = packlohi(v.x, v.y);
            o.y = packlohi(v.z, v.w);
            *(uint2*)(xb + (size_t)i * 4) = o;
            *(float4*)(y + (size_t)i * 4) = v;   // y init = x (residual)
        }
    }
}

__device__ __forceinline__ float gelu(float v) {
    return 0.5f * v * (1.f + erff(v * 0.70710678118654752f));
}

// ---------------- grouped GEMM: bf16 m16n8k16, cross-work pipelined ---------
// FIRST: g_hb = bf16(gelu(gather(g_xb) @ W1 + b1)),  N=HID, K=DIM
// else : y[tok] += w_slot * (g_hb @ W2 + b2)  (fused combine, fp32 atomics)
// Per-CTA inline scan of g_cnt replaces the former k_scan kernel.
#define A_W  (128 * 20)
#define B_W  (16 * 136)
#define ST_W (A_W + B_W)            // 4736 words
#define ST_B ((uint32_t)(ST_W * 4)) // 18944 bytes
#define GEMM_SMEM (4 * ST_W * 4)    // 75776 bytes

template <bool FIRST>
__global__ void __launch_bounds__(256, 2)
k_gemm(const __nv_bfloat16* __restrict__ Bw,   // pair-packed words
       const float* __restrict__ bias,
       float* __restrict__ yout) {
    constexpr int N   = FIRST ? HID : DIM;
    constexpr int K   = FIRST ? DIM : HID;
    constexpr int KT  = K / 32;
    constexpr int NT  = N / 128;

    extern __shared__ uint32_t dsw[];
    const uint32_t sb = smem_u32(dsw);
    __shared__ int s_off[NE + 1];
    __shared__ int s_tp[NE + 1];

    const int tid  = threadIdx.x;
    const int lane = tid & 31;
    const int wid  = tid >> 5;
    const int wm   = (wid & 3) * 32;
    const int wn   = (wid >> 2) * 64;
    const int g    = lane >> 2;
    const int t    = lane & 3;

    if (tid == 0) {
        int o = 0, tp = 0;
        s_off[0] = 0; s_tp[0] = 0;
#pragma unroll
        for (int e = 0; e < NE; e++) {
            int c = g_cnt[e];
            o += c; tp += (c + 127) / 128;
            s_off[e + 1] = o; s_tp[e + 1] = tp;
        }
    }
    __syncthreads();

    const int total = s_tp[NE] * NT;
    int work = blockIdx.x;
    if (work >= total) return;

    auto desc = [&](int wk, int& m0, int& mEnd, int& n0, int& e,
                    const char*& Bep) {
        int mt = wk / NT;
        int nt = wk - mt * NT;
        e = 0;
        while (s_tp[e + 1] <= mt) e++;
        m0   = s_off[e] + (mt - s_tp[e]) * 128;
        mEnd = s_off[e + 1];
        n0   = nt * 128;
        Bep  = (const char*)Bw + ((size_t)e * (K / 2) * N + n0) * 4;
    };

    auto load_tile = [&](int m0, int mEnd, const char* Bep, int kt, int s) {
        const uint32_t ab = sb + (uint32_t)s * ST_B;
        const uint32_t bb = ab + A_W * 4;
#pragma unroll
        for (int j = 0; j < 2; j++) {
            int idx = tid + j * 256;
            int row = idx >> 2, c = idx & 3;
            int rg = min(m0 + row, mEnd - 1);
            const char* src;
            if (FIRST)
                src = (const char*)g_xb
                    + ((size_t)g_slot_token[rg] * DIM + kt * 32) * 2 + c * 16;
            else
                src = (const char*)g_hb
                    + ((size_t)rg * HID + kt * 32) * 2 + c * 16;
            CP_ASYNC16(ab + (uint32_t)(row * 80 + c * 16), src);
        }
#pragma unroll
        for (int j = 0; j < 2; j++) {
            int idx = tid + j * 256;
            int row = idx >> 5, c = idx & 31;
            const char* src = Bep + ((size_t)(kt * 16 + row) * N) * 4 + c * 16;
            CP_ASYNC16(bb + (uint32_t)(row * 544 + c * 16), src);
        }
    };

    int m0, mEnd, n0, e;
    const char* Bep;
    desc(work, m0, mEnd, n0, e, Bep);

    load_tile(m0, mEnd, Bep, 0, 0); CP_COMMIT();
    load_tile(m0, mEnd, Bep, 1, 1); CP_COMMIT();
    load_tile(m0, mEnd, Bep, 2, 2); CP_COMMIT();

    for (;;) {
        const int nwork = work + gridDim.x;
        const bool has_next = nwork < total;
        int nm0, nmEnd, nn0, ne;
        const char* nBep;
        if (has_next) desc(nwork, nm0, nmEnd, nn0, ne, nBep);

        float acc[2][8][4];
#pragma unroll
        for (int mi = 0; mi < 2; mi++)
#pragma unroll
            for (int ni = 0; ni < 8; ni++)
#pragma unroll
                for (int q = 0; q < 4; q++) acc[mi][ni][q] = 0.f;

        for (int i = 0; i < KT; i++) {
            CP_WAIT2();
            __syncthreads();
            const int s = i & 3;
            const uint32_t* Aw = dsw + (size_t)s * ST_W;
            const uint32_t* Bs = Aw + A_W;
#pragma unroll
            for (int ks = 0; ks < 2; ks++) {
                uint32_t af[2][4];
#pragma unroll
                for (int mi = 0; mi < 2; mi++) {
                    const int r = wm + mi * 16 + g;
                    af[mi][0] = Aw[r * 20 + ks * 8 + t];
                    af[mi][1] = Aw[(r + 8) * 20 + ks * 8 + t];
                    af[mi][2] = Aw[r * 20 + ks * 8 + 4 + t];
                    af[mi][3] = Aw[(r + 8) * 20 + ks * 8 + 4 + t];
                }
                const int kp = ks * 8 + t;
#pragma unroll
                for (int ni = 0; ni < 8; ni++) {
                    const int cn = wn + ni * 8 + g;
                    uint32_t b0 = Bs[kp * 136 + cn];
                    uint32_t b1 = Bs[(kp + 4) * 136 + cn];
                    MMA_BF16(acc[0][ni], af[0][0], af[0][1], af[0][2], af[0][3], b0, b1);
                    MMA_BF16(acc[1][ni], af[1][0], af[1][1], af[1][2], af[1][3], b0, b1);
                }
            }
            if (i + 3 < KT)
                load_tile(m0, mEnd, Bep, i + 3, (i + 3) & 3);
            else if (has_next)
                load_tile(nm0, nmEnd, nBep, i + 3 - KT, (i + 3) & 3);
            CP_COMMIT();
        }

        // epilogue — overlaps next work's prologue cp.asyncs
#pragma unroll
        for (int mi = 0; mi < 2; mi++) {
            const int row0 = m0 + wm + mi * 16 + g;
            const int row1 = row0 + 8;
            int   tok0 = 0, tok1 = 0;
            float ws0 = 0.f, ws1 = 0.f;
            if (!FIRST) {
                if (row0 < mEnd) { tok0 = g_slot_token[row0]; ws0 = g_tws[row0]; }
                if (row1 < mEnd) { tok1 = g_slot_token[row1]; ws1 = g_tws[row1]; }
            }
#pragma unroll
            for (int ni = 0; ni < 8; ni++) {
                const int col = n0 + wn + ni * 8 + 2 * t;
                const float2 bb = *(const float2*)(bias + e * N + col);
                float v0 = acc[mi][ni][0] + bb.x;
                float v1 = acc[mi][ni][1] + bb.y;
                float v2 = acc[mi][ni][2] + bb.x;
                float v3 = acc[mi][ni][3] + bb.y;
                if (FIRST) {
                    v0 = gelu(v0); v1 = gelu(v1); v2 = gelu(v2); v3 = gelu(v3);
                    uint32_t p0 = packlohi(v0, v1);
                    uint32_t p1 = packlohi(v2, v3);
                    if (row0 < mEnd)
                        *(uint32_t*)(g_hb + (size_t)row0 * HID + col) = p0;
                    if (row1 < mEnd)
                        *(uint32_t*)(g_hb + (size_t)row1 * HID + col) = p1;
                } else {
                    if (row0 < mEnd) {
                        float* yp = yout + (size_t)tok0 * DIM + col;
                        atomicAdd(yp,     ws0 * v0);
                        atomicAdd(yp + 1, ws0 * v1);
                    }
                    if (row1 < mEnd) {
                        float* yp = yout + (size_t)tok1 * DIM + col;
                        atomicAdd(yp,     ws1 * v2);
                        atomicAdd(yp + 1, ws1 * v3);
                    }
                }
            }
        }

        if (!has_next) break;
        work = nwork;
        m0 = nm0; mEnd = nmEnd; n0 = nn0; e = ne; Bep = nBep;
    }
}

// ---------------- launch -----------------------------------------------------
extern "C" void kernel_launch(void* const* d_in, const int* in_sizes, int n_in,
                              void* d_out, int out_size) {
    const float* x  = (const float*)d_in[0];
    const float* Wr = (const float*)d_in[1];
    const float* br = (const float*)d_in[2];
    const float* W1 = (const float*)d_in[3];
    const float* b1 = (const float*)d_in[4];
    const float* W2 = (const float*)d_in[5];
    const float* b2 = (const float*)d_in[6];
    float* y = (float*)d_out;
    const int T = in_sizes[0] / DIM;

    cudaFuncSetAttribute(k_gemm<true>,  cudaFuncAttributeMaxDynamicSharedMemorySize, GEMM_SMEM);
    cudaFuncSetAttribute(k_gemm<false>, cudaFuncAttributeMaxDynamicSharedMemorySize, GEMM_SMEM);

    __nv_bfloat16* w1p; cudaGetSymbolAddress((void**)&w1p, g_w1p);
    __nv_bfloat16* w2p; cudaGetSymbolAddress((void**)&w2p, g_w2p);
    __nv_bfloat16* xb;  cudaGetSymbolAddress((void**)&xb,  g_xb);

    {
        int xblk = (T * (DIM / 4) + 255) / 256;
        k_prep<<<2 * WSEG + xblk, 256>>>(W1, W2, x, w1p, w2p, xb, y, T);
    }
    k_router<<<(T + 31) / 32, 256>>>(x, Wr, br, T);
    k_scatter<<<(2 * T + 255) / 256, 256>>>(T);

    k_gemm<true ><<<296, 256, GEMM_SMEM>>>(w1p, b1, nullptr);
    k_gemm<false><<<296, 256, GEMM_SMEM>>>(w2p, b2, y);
}

// round 16
// speedup vs baseline: 1.0601x; 1.0601x over previous
#include <cuda_runtime.h>
#include <cuda_bf16.h>
#include <math.h>
#include <stdint.h>

#define NE 16
#define DIM 512
#define HID 1024
#define MAXT 8192
#define MAXSLOTS (MAXT * 2)

// ---------------- scratch (device globals; no allocation allowed) ----------
__device__ int   g_cnt[NE];
__device__ int   g_off[NE + 1];
__device__ int   g_tp[NE + 1];
__device__ int   g_tidx[MAXSLOTS];
__device__ int   g_rank[MAXSLOTS];
__device__ float g_tw[MAXSLOTS];
__device__ int   g_slot_token[MAXSLOTS];
__device__ float g_tws[MAXSLOTS];                        // weight per slot
__device__ __nv_bfloat16 g_xb[(size_t)MAXT * DIM];       // x bf16 (same layout)
__device__ __nv_bfloat16 g_hb[(size_t)MAXSLOTS * HID];   // gelu(h) bf16
// weights, k-pair packed: word(kp,n) = {lo=W[2kp][n], hi=W[2kp+1][n]} bf16x2
__device__ __nv_bfloat16 g_w1p[(size_t)NE * DIM * HID];  // [E][DIM/2][HID] words
__device__ __nv_bfloat16 g_w2p[(size_t)NE * HID * DIM];  // [E][HID/2][DIM] words

// ---------------- PTX helpers ------------------------------------------------
__device__ __forceinline__ uint32_t smem_u32(const void* p) {
    uint32_t a;
    asm("{ .reg .u64 t; cvta.to.shared.u64 t, %1; cvt.u32.u64 %0, t; }"
        : "=r"(a) : "l"(p));
    return a;
}

#define CP_ASYNC16(dst, src) \
    asm volatile("cp.async.cg.shared.global [%0], [%1], 16;" \
                 :: "r"(dst), "l"(src) : "memory")
#define CP_COMMIT() asm volatile("cp.async.commit_group;" ::: "memory")
#define CP_WAIT1()  asm volatile("cp.async.wait_group 1;"  ::: "memory")

#define MMA_BF16(c, a0, a1, a2, a3, b0, b1) \
    asm volatile("mma.sync.aligned.m16n8k16.row.col.f32.bf16.bf16.f32 " \
                 "{%0,%1,%2,%3}, {%4,%5,%6,%7}, {%8,%9}, {%0,%1,%2,%3};" \
                 : "+f"((c)[0]), "+f"((c)[1]), "+f"((c)[2]), "+f"((c)[3]) \
                 : "r"(a0), "r"(a1), "r"(a2), "r"(a3), "r"(b0), "r"(b1))

// pack {lo, hi} fp32 -> bf16x2 (src0 = hi, src1 = lo; verified rounds 7-15)
__device__ __forceinline__ uint32_t packlohi(float lo, float hi) {
    uint32_t d;
    asm("cvt.rn.bf16x2.f32 %0, %1, %2;" : "=r"(d) : "f"(hi), "f"(lo));
    return d;
}

// ---------------- small kernels (round-14 chain, verified 202.8us) ----------
__global__ void k_init() { if (threadIdx.x < NE) g_cnt[threadIdx.x] = 0; }

__global__ void __launch_bounds__(256)
k_router(const float* __restrict__ x, const float* __restrict__ Wr,
         const float* __restrict__ br, int T) {
    __shared__ float wrs[DIM * 17];
    for (int i = threadIdx.x; i < DIM * NE; i += 256) {
        int d = i >> 4, e = i & 15;
        wrs[d * 17 + e] = Wr[i];
    }
    __syncthreads();

    const int lane = threadIdx.x & 31;
    const int w    = threadIdx.x >> 5;
    const int q    = lane & 7;
    const int tok  = blockIdx.x * 32 + w * 4 + (lane >> 3);
    const int tokc = min(tok, T - 1);

    float acc[NE];
#pragma unroll
    for (int e = 0; e < NE; e++) acc[e] = 0.f;

    const float* xr = x + (size_t)tokc * DIM;
#pragma unroll 4
    for (int i = 0; i < DIM / 8; i++) {
        const int d = i * 8 + q;
        const float xs = xr[d];
        const float* wrow = wrs + d * 17;
#pragma unroll
        for (int e = 0; e < NE; e++) acc[e] = fmaf(xs, wrow[e], acc[e]);
    }
#pragma unroll
    for (int off = 1; off <= 4; off <<= 1)
#pragma unroll
        for (int e = 0; e < NE; e++)
            acc[e] += __shfl_xor_sync(0xffffffffu, acc[e], off);

    if (q == 0 && tok < T) {
        float l[NE];
#pragma unroll
        for (int e = 0; e < NE; e++) l[e] = acc[e] + br[e];
        int b0 = 0; float l0 = l[0];
#pragma unroll
        for (int e = 1; e < NE; e++) if (l[e] > l0) { l0 = l[e]; b0 = e; }
        int b1 = -1; float l1 = -3.0e38f;
#pragma unroll
        for (int e = 0; e < NE; e++)
            if (e != b0 && l[e] > l1) { l1 = l[e]; b1 = e; }
        float w0 = 1.f / (1.f + expf(l1 - l0));
        g_tidx[2 * tok] = b0; g_tidx[2 * tok + 1] = b1;
        g_tw[2 * tok] = w0;   g_tw[2 * tok + 1] = 1.f - w0;
        g_rank[2 * tok]     = atomicAdd(&g_cnt[b0], 1);
        g_rank[2 * tok + 1] = atomicAdd(&g_cnt[b1], 1);
    }
}

__global__ void k_scan() {
    if (threadIdx.x == 0) {
        g_off[0] = 0; g_tp[0] = 0;
        for (int e = 0; e < NE; e++) {
            int c = g_cnt[e];
            g_off[e + 1] = g_off[e] + c;
            g_tp[e + 1] = g_tp[e] + (c + 127) / 128;
        }
    }
}

__global__ void k_scatter(int T) {
    int i = blockIdx.x * blockDim.x + threadIdx.x;
    if (i >= 2 * T) return;
    int pos = g_off[g_tidx[i]] + g_rank[i];
    g_slot_token[pos] = i >> 1;
    g_tws[pos]        = g_tw[i];
}

// merged prep: W1 pair-pack | W2 pair-pack | x -> (xb bf16, y = x copy)
__device__ __forceinline__ void pairpack(const float* __restrict__ W,
                                         __nv_bfloat16* __restrict__ Wp,
                                         int KK, int NN, int i) {
    int nq4 = NN / 4;
    int nq = i % nq4;
    int rest = i / nq4;
    int kp = rest % (KK / 2);
    int e  = rest / (KK / 2);
    const float* base = W + ((size_t)e * KK + 2 * kp) * NN + nq * 4;
    float4 r0 = *(const float4*)base;
    float4 r1 = *(const float4*)(base + NN);
    uint4 o;
    o.x = packlohi(r0.x, r1.x);
    o.y = packlohi(r0.y, r1.y);
    o.z = packlohi(r0.z, r1.z);
    o.w = packlohi(r0.w, r1.w);
    *(uint4*)(Wp + (((size_t)e * (KK / 2) + kp) * NN + nq * 4) * 2) = o;
}

#define WSEG 4096

__global__ void __launch_bounds__(256)
k_prep(const float* __restrict__ W1, const float* __restrict__ W2,
       const float* __restrict__ x,
       __nv_bfloat16* __restrict__ w1p, __nv_bfloat16* __restrict__ w2p,
       __nv_bfloat16* __restrict__ xb, float* __restrict__ y, int T) {
    int b = blockIdx.x;
    if (b < WSEG) {
        pairpack(W1, w1p, DIM, HID, b * 256 + threadIdx.x);
    } else if (b < 2 * WSEG) {
        pairpack(W2, w2p, HID, DIM, (b - WSEG) * 256 + threadIdx.x);
    } else {
        int i = (b - 2 * WSEG) * 256 + threadIdx.x;
        if (i < T * (DIM / 4)) {
            float4 v = *(const float4*)(x + (size_t)i * 4);
            uint2 o;
            o.x = packlohi(v.x, v.y);
            o.y = packlohi(v.z, v.w);
            *(uint2*)(xb + (size_t)i * 4) = o;
            *(float4*)(y + (size_t)i * 4) = v;   // y init = x (residual)
        }
    }
}

__device__ __forceinline__ float gelu(float v) {
    return 0.5f * v * (1.f + erff(v * 0.70710678118654752f));
}

// ---------------- grouped GEMM: bf16 m16n8k16, BK=64, 3-stage ---------------
// FIRST: g_hb = bf16(gelu(gather(g_xb) @ W1 + b1)),  N=HID, K=DIM
// else : y[tok] += w_slot * (g_hb @ W2 + b2)  (fused combine, fp32 atomics)
// A stage: bf16, 128 rows x (32+4) words, stride 36 (144B rows; the exact
//          stride-36 bank pattern verified conflict-free in round 8)
// B stage: pair-packed, 32 kp-rows x (128+8) words, stride 136 (verified r12)
// ONE __syncthreads + ONE wait per 64-k (half of round 14's density).
#define A_W  (128 * 36)
#define B_W  (32 * 136)
#define ST_W (A_W + B_W)            // 8960 words
#define ST_B ((uint32_t)(ST_W * 4)) // 35840 bytes
#define GEMM_SMEM (3 * ST_W * 4)    // 107520 bytes (2 CTAs/SM: 215KB <= 227KB)

template <bool FIRST>
__global__ void __launch_bounds__(256, 2)
k_gemm(const __nv_bfloat16* __restrict__ Bw,   // pair-packed words
       const float* __restrict__ bias,
       float* __restrict__ yout) {
    constexpr int N   = FIRST ? HID : DIM;
    constexpr int K   = FIRST ? DIM : HID;
    constexpr int KT  = K / 64;                 // 8 or 16
    constexpr int NT  = N / 128;

    extern __shared__ uint32_t dsw[];
    const uint32_t sb = smem_u32(dsw);

    const int tid  = threadIdx.x;
    const int lane = tid & 31;
    const int wid  = tid >> 5;
    const int wm   = (wid & 3) * 32;
    const int wn   = (wid >> 2) * 64;
    const int g    = lane >> 2;
    const int t    = lane & 3;

    const int total = g_tp[NE] * NT;
    int work = blockIdx.x;
    if (work >= total) return;

    auto desc = [&](int wk, int& m0, int& mEnd, int& n0, int& e,
                    const char*& Bep) {
        int mt = wk / NT;
        int nt = wk - mt * NT;
        e = 0;
        while (g_tp[e + 1] <= mt) e++;
        m0   = g_off[e] + (mt - g_tp[e]) * 128;
        mEnd = g_off[e + 1];
        n0   = nt * 128;
        Bep  = (const char*)Bw + ((size_t)e * (K / 2) * N + n0) * 4;
    };

    // loader for one BK=64 tile into stage s
    auto load_tile = [&](int m0, int mEnd, const char* Bep, int kt, int s) {
        const uint32_t ab = sb + (uint32_t)s * ST_B;
        const uint32_t bb = ab + A_W * 4;
        // A: 128 rows x 128B (8 chunks of 16B), dst stride 144B
#pragma unroll
        for (int j = 0; j < 4; j++) {
            int idx = tid + j * 256;
            int row = idx >> 3, c = idx & 7;
            int rg = min(m0 + row, mEnd - 1);
            const char* src;
            if (FIRST)
                src = (const char*)g_xb
                    + ((size_t)g_slot_token[rg] * DIM + kt * 64) * 2 + c * 16;
            else
                src = (const char*)g_hb
                    + ((size_t)rg * HID + kt * 64) * 2 + c * 16;
            CP_ASYNC16(ab + (uint32_t)(row * 144 + c * 16), src);
        }
        // B: 32 kp-rows x 512B (32 chunks of 16B), dst stride 544B
#pragma unroll
        for (int j = 0; j < 4; j++) {
            int idx = tid + j * 256;
            int row = idx >> 5, c = idx & 31;
            const char* src = Bep + ((size_t)(kt * 32 + row) * N) * 4 + c * 16;
            CP_ASYNC16(bb + (uint32_t)(row * 544 + c * 16), src);
        }
    };

    int m0, mEnd, n0, e;
    const char* Bep;
    desc(work, m0, mEnd, n0, e, Bep);

    // prologue: 2 tiles in flight (stages 0, 1)
    load_tile(m0, mEnd, Bep, 0, 0); CP_COMMIT();
    load_tile(m0, mEnd, Bep, 1, 1); CP_COMMIT();
    int cs = 0;   // compute stage, persists across work items

    for (;;) {
        const int nwork = work + gridDim.x;
        const bool has_next = nwork < total;
        int nm0, nmEnd, nn0, ne;
        const char* nBep;
        if (has_next) desc(nwork, nm0, nmEnd, nn0, ne, nBep);

        float acc[2][8][4];
#pragma unroll
        for (int mi = 0; mi < 2; mi++)
#pragma unroll
            for (int ni = 0; ni < 8; ni++)
#pragma unroll
                for (int q = 0; q < 4; q++) acc[mi][ni][q] = 0.f;

        for (int i = 0; i < KT; i++) {
            CP_WAIT1();          // tile i resident (<=1 group pending)
            __syncthreads();     // also orders iter i-1 reads before the
                                 // load below into stage (cs+2)%3
            const uint32_t* Aw = dsw + (size_t)cs * ST_W;
            const uint32_t* Bs = Aw + A_W;
#pragma unroll
            for (int ks = 0; ks < 4; ks++) {     // four k16 steps per BK64
                uint32_t af[2][4];
#pragma unroll
                for (int mi = 0; mi < 2; mi++) {
                    const int r = wm + mi * 16 + g;
                    af[mi][0] = Aw[r * 36 + ks * 8 + t];
                    af[mi][1] = Aw[(r + 8) * 36 + ks * 8 + t];
                    af[mi][2] = Aw[r * 36 + ks * 8 + 4 + t];
                    af[mi][3] = Aw[(r + 8) * 36 + ks * 8 + 4 + t];
                }
                const int kp = ks * 8 + t;
#pragma unroll
                for (int ni = 0; ni < 8; ni++) {
                    const int cn = wn + ni * 8 + g;
                    uint32_t b0 = Bs[kp * 136 + cn];
                    uint32_t b1 = Bs[(kp + 4) * 136 + cn];
                    MMA_BF16(acc[0][ni], af[0][0], af[0][1], af[0][2], af[0][3], b0, b1);
                    MMA_BF16(acc[1][ni], af[1][0], af[1][1], af[1][2], af[1][3], b0, b1);
                }
            }
            int ls = cs + 2; if (ls >= 3) ls -= 3;
            if (i + 2 < KT)
                load_tile(m0, mEnd, Bep, i + 2, ls);
            else if (has_next)
                load_tile(nm0, nmEnd, nBep, i + 2 - KT, ls);
            CP_COMMIT();
            cs = cs + 1; if (cs >= 3) cs -= 3;
        }

        // epilogue (verified r14) — overlaps next work's loads
#pragma unroll
        for (int mi = 0; mi < 2; mi++) {
            const int row0 = m0 + wm + mi * 16 + g;
            const int row1 = row0 + 8;
            int   tok0 = 0, tok1 = 0;
            float ws0 = 0.f, ws1 = 0.f;
            if (!FIRST) {
                if (row0 < mEnd) { tok0 = g_slot_token[row0]; ws0 = g_tws[row0]; }
                if (row1 < mEnd) { tok1 = g_slot_token[row1]; ws1 = g_tws[row1]; }
            }
#pragma unroll
            for (int ni = 0; ni < 8; ni++) {
                const int col = n0 + wn + ni * 8 + 2 * t;
                const float2 bb = *(const float2*)(bias + e * N + col);
                float v0 = acc[mi][ni][0] + bb.x;
                float v1 = acc[mi][ni][1] + bb.y;
                float v2 = acc[mi][ni][2] + bb.x;
                float v3 = acc[mi][ni][3] + bb.y;
                if (FIRST) {
                    v0 = gelu(v0); v1 = gelu(v1); v2 = gelu(v2); v3 = gelu(v3);
                    uint32_t p0 = packlohi(v0, v1);
                    uint32_t p1 = packlohi(v2, v3);
                    if (row0 < mEnd)
                        *(uint32_t*)(g_hb + (size_t)row0 * HID + col) = p0;
                    if (row1 < mEnd)
                        *(uint32_t*)(g_hb + (size_t)row1 * HID + col) = p1;
                } else {
                    if (row0 < mEnd) {
                        float* yp = yout + (size_t)tok0 * DIM + col;
                        atomicAdd(yp,     ws0 * v0);
                        atomicAdd(yp + 1, ws0 * v1);
                    }
                    if (row1 < mEnd) {
                        float* yp = yout + (size_t)tok1 * DIM + col;
                        atomicAdd(yp,     ws1 * v2);
                        atomicAdd(yp + 1, ws1 * v3);
                    }
                }
            }
        }

        if (!has_next) break;
        work = nwork;
        m0 = nm0; mEnd = nmEnd; n0 = nn0; e = ne; Bep = nBep;
    }
}

// ---------------- launch -----------------------------------------------------
extern "C" void kernel_launch(void* const* d_in, const int* in_sizes, int n_in,
                              void* d_out, int out_size) {
    const float* x  = (const float*)d_in[0];
    const float* Wr = (const float*)d_in[1];
    const float* br = (const float*)d_in[2];
    const float* W1 = (const float*)d_in[3];
    const float* b1 = (const float*)d_in[4];
    const float* W2 = (const float*)d_in[5];
    const float* b2 = (const float*)d_in[6];
    float* y = (float*)d_out;
    const int T = in_sizes[0] / DIM;

    cudaFuncSetAttribute(k_gemm<true>,  cudaFuncAttributeMaxDynamicSharedMemorySize, GEMM_SMEM);
    cudaFuncSetAttribute(k_gemm<false>, cudaFuncAttributeMaxDynamicSharedMemorySize, GEMM_SMEM);

    __nv_bfloat16* w1p; cudaGetSymbolAddress((void**)&w1p, g_w1p);
    __nv_bfloat16* w2p; cudaGetSymbolAddress((void**)&w2p, g_w2p);
    __nv_bfloat16* xb;  cudaGetSymbolAddress((void**)&xb,  g_xb);

    k_init<<<1, 32>>>();
    {
        int xblk = (T * (DIM / 4) + 255) / 256;
        k_prep<<<2 * WSEG + xblk, 256>>>(W1, W2, x, w1p, w2p, xb, y, T);
    }
    k_router<<<(T + 31) / 32, 256>>>(x, Wr, br, T);
    k_scan<<<1, 32>>>();
    k_scatter<<<(2 * T + 255) / 256, 256>>>(T);

    k_gemm<true ><<<296, 256, GEMM_SMEM>>>(w1p, b1, nullptr);
    k_gemm<false><<<296, 256, GEMM_SMEM>>>(w2p, b2, y);
}